// round 16
// baseline (speedup 1.0000x reference)
#include <cuda_runtime.h>
#include <cuda_bf16.h>

// loss_i = (label_i == label[N-1]) ? d2 : max(0, MARGIN - d2),  d2 = ||p_{N-1}-p_i||^2, D=3
// Output: scalar sum. SINGLE graph node. Specialized kernel for N=32768
// (64 CTAs x 128 thr, 4 pts/thread, no bounds checks, no params beyond
// pointers); generic fallback otherwise. Per-warp fire-and-forget RED publish
// (relaxed accum + release arrival count), no __syncthreads in the hot path.
// One thread (CTA0/T0) tight-polls with ld.acquire, then reads+resets the
// accumulator in one atom.acquire.exch, writes out[0], resets the counter.
// All 64 CTAs are co-resident (single wave) -> spin is deadlock-free.
// Allocation-free, graph-capturable, deterministic work per call.

#define MARGIN 500.0f
#define TPB 128
#define PTS_PER_THREAD 4
#define N_FIXED 32768
#define BLOCKS_FIXED (N_FIXED / (TPB * PTS_PER_THREAD))          /* 64  */
#define WARPS_FIXED  (BLOCKS_FIXED * (TPB / 32))                 /* 256 */

__device__ float        g_accum = 0.0f;
__device__ unsigned int g_count = 0u;

__device__ __forceinline__ void red_add_f32_relaxed(float* p, float v) {
    asm volatile("red.relaxed.gpu.add.f32 [%0], %1;" :: "l"(p), "f"(v) : "memory");
}
__device__ __forceinline__ void red_add_u32_release(unsigned* p, unsigned v) {
    asm volatile("red.release.gpu.add.u32 [%0], %1;" :: "l"(p), "r"(v) : "memory");
}
__device__ __forceinline__ unsigned ld_u32_acquire(const unsigned* p) {
    unsigned v;
    asm volatile("ld.acquire.gpu.u32 %0, [%1];" : "=r"(v) : "l"(p) : "memory");
    return v;
}
__device__ __forceinline__ float atom_exch_f32_acquire(float* p, float v) {
    unsigned old;
    asm volatile("atom.acquire.gpu.exch.b32 %0, [%1], %2;"
                 : "=r"(old) : "l"(p), "r"(__float_as_uint(v)) : "memory");
    return __uint_as_float(old);
}
__device__ __forceinline__ void st_u32_relaxed(unsigned* p, unsigned v) {
    asm volatile("st.relaxed.gpu.u32 [%0], %1;" :: "l"(p), "r"(v) : "memory");
}

__device__ __forceinline__ float pair_loss(float ax, float ay, float az, int al,
                                           float px, float py, float pz, int pl) {
    const float dx = ax - px, dy = ay - py, dz = az - pz;
    const float d2 = fmaf(dx, dx, fmaf(dy, dy, dz * dz));
    return (pl == al) ? d2 : fmaxf(0.0f, MARGIN - d2);
}

// ---- Specialized: N = 32768 exactly. No bounds checks, no size params. ----
__global__ __launch_bounds__(TPB)
void loss_kernel_32768(const int* __restrict__ labels,
                       const float* __restrict__ coords,
                       float* __restrict__ out)
{
    const int base = (blockIdx.x * TPB + threadIdx.x) * PTS_PER_THREAD;

    // Wide loads, all independent -> batched MLP. 48B/thread -> 16B aligned.
    const int4    lab = *reinterpret_cast<const int4*>(labels + base);
    const float4* cp  = reinterpret_cast<const float4*>(coords + 3 * base);
    const float4  c0 = cp[0], c1 = cp[1], c2 = cp[2];

    // Anchor: same 2 cache lines chip-wide -> L1 broadcast.
    const int   al = __ldg(labels + (N_FIXED - 1));
    const float ax = __ldg(coords + 3 * (N_FIXED - 1) + 0);
    const float ay = __ldg(coords + 3 * (N_FIXED - 1) + 1);
    const float az = __ldg(coords + 3 * (N_FIXED - 1) + 2);

    // p0=(c0.x,c0.y,c0.z) p1=(c0.w,c1.x,c1.y) p2=(c1.z,c1.w,c2.x) p3=(c2.y,c2.z,c2.w)
    float v;
    v  = pair_loss(ax, ay, az, al, c0.x, c0.y, c0.z, lab.x);
    v += pair_loss(ax, ay, az, al, c0.w, c1.x, c1.y, lab.y);
    v += pair_loss(ax, ay, az, al, c1.z, c1.w, c2.x, lab.z);
    v += pair_loss(ax, ay, az, al, c2.y, c2.z, c2.w, lab.w);

    #pragma unroll
    for (int o = 16; o > 0; o >>= 1)
        v += __shfl_down_sync(0xFFFFFFFFu, v, o);

    if ((threadIdx.x & 31) == 0) {
        red_add_f32_relaxed(&g_accum, v);    // fire-and-forget
        red_add_u32_release(&g_count, 1u);   // release orders the RED
    }

    if (blockIdx.x == 0 && threadIdx.x == 0) {
        while (ld_u32_acquire(&g_count) != (unsigned)WARPS_FIXED) { }
        out[0] = atom_exch_f32_acquire(&g_accum, 0.0f);  // read + reset in one op
        st_u32_relaxed(&g_count, 0u);                     // reset for next replay
    }
}

// ---- Generic fallback for any n (correctness safety net). ----
__global__ __launch_bounds__(TPB)
void loss_kernel_generic(const int* __restrict__ labels,
                         const float* __restrict__ coords,
                         float* __restrict__ out,
                         int n, unsigned int total_warps)
{
    const int base = (blockIdx.x * TPB + threadIdx.x) * PTS_PER_THREAD;

    const int   al = __ldg(labels + (n - 1));
    const float ax = __ldg(coords + 3 * (n - 1) + 0);
    const float ay = __ldg(coords + 3 * (n - 1) + 1);
    const float az = __ldg(coords + 3 * (n - 1) + 2);

    float v = 0.0f;
    for (int i = base; i < n && i < base + PTS_PER_THREAD; i++)
        v += pair_loss(ax, ay, az, al,
                       coords[3 * i + 0], coords[3 * i + 1], coords[3 * i + 2],
                       labels[i]);

    #pragma unroll
    for (int o = 16; o > 0; o >>= 1)
        v += __shfl_down_sync(0xFFFFFFFFu, v, o);

    if ((threadIdx.x & 31) == 0) {
        red_add_f32_relaxed(&g_accum, v);
        red_add_u32_release(&g_count, 1u);
    }

    if (blockIdx.x == 0 && threadIdx.x == 0) {
        while (ld_u32_acquire(&g_count) != total_warps) { }
        out[0] = atom_exch_f32_acquire(&g_accum, 0.0f);
        st_u32_relaxed(&g_count, 0u);
    }
}

extern "C" void kernel_launch(void* const* d_in, const int* in_sizes, int n_in,
                              void* d_out, int out_size)
{
    const int*   labels = (const int*)d_in[0];
    const float* coords = (const float*)d_in[1];
    float*       out    = (float*)d_out;
    const int n = in_sizes[0];

    if (n == N_FIXED) {
        loss_kernel_32768<<<BLOCKS_FIXED, TPB>>>(labels, coords, out);
    } else {
        const int pts_per_cta = TPB * PTS_PER_THREAD;
        const int blocks = (n + pts_per_cta - 1) / pts_per_cta;
        const unsigned total_warps = (unsigned)blocks * (TPB / 32);
        loss_kernel_generic<<<blocks, TPB>>>(labels, coords, out, n, total_warps);
    }
}

// round 17
// speedup vs baseline: 1.0483x; 1.0483x over previous
#include <cuda_runtime.h>
#include <cuda_bf16.h>

// loss_i = (label_i == label[N-1]) ? d2 : max(0, MARGIN - d2),  d2 = ||p_{N-1}-p_i||^2, D=3
// Output: scalar sum.
//
// Two graph nodes (measured-best graph shape, R9 = dur_us 6.624 / kernel 4.38us):
//   node 1: 1-thread zero of out[0]
//   node 2: 64 CTAs x 128 thr; each thread handles 4 points via 4 independent
//           16B loads; 5-shfl warp reduce; warp leader issues ONE fire-and-
//           forget red.relaxed into out[0]. No device globals, no counter,
//           no spin, no fences — the minimal possible completion tail.
// Stream order inside the graph orders the zero before all REDs on every
// replay; kernel-boundary semantics make the REDs visible to the harness.
// Specialized no-bounds-check kernel for N=32768 (regs ~30); generic fallback
// otherwise. Allocation-free, graph-capturable, deterministic work per call
// (fp atomic ordering -> ~1e-7 rel err, far under the 1e-3 gate).

#define MARGIN 500.0f
#define TPB 128
#define PTS_PER_THREAD 4
#define N_FIXED 32768
#define BLOCKS_FIXED (N_FIXED / (TPB * PTS_PER_THREAD))   /* 64 */

__global__ void zero_out_kernel(float* __restrict__ out) {
    out[0] = 0.0f;
}

__device__ __forceinline__ void red_add_f32_relaxed(float* p, float v) {
    asm volatile("red.relaxed.gpu.add.f32 [%0], %1;" :: "l"(p), "f"(v) : "memory");
}

__device__ __forceinline__ float pair_loss(float ax, float ay, float az, int al,
                                           float px, float py, float pz, int pl) {
    const float dx = ax - px, dy = ay - py, dz = az - pz;
    const float d2 = fmaf(dx, dx, fmaf(dy, dy, dz * dz));
    return (pl == al) ? d2 : fmaxf(0.0f, MARGIN - d2);
}

// ---- Specialized: N = 32768 exactly. No bounds checks, no size params. ----
__global__ __launch_bounds__(TPB)
void loss_kernel_32768(const int* __restrict__ labels,
                       const float* __restrict__ coords,
                       float* __restrict__ out)
{
    const int base = (blockIdx.x * TPB + threadIdx.x) * PTS_PER_THREAD;

    // 4 independent wide loads, issued up front (batched MLP).
    // 48B/thread -> every float4 is 16B aligned.
    const int4    lab = *reinterpret_cast<const int4*>(labels + base);
    const float4* cp  = reinterpret_cast<const float4*>(coords + 3 * base);
    const float4  c0 = cp[0], c1 = cp[1], c2 = cp[2];

    // Anchor: same 2 cache lines chip-wide -> L1 broadcast (overlaps above).
    const int   al = __ldg(labels + (N_FIXED - 1));
    const float ax = __ldg(coords + 3 * (N_FIXED - 1) + 0);
    const float ay = __ldg(coords + 3 * (N_FIXED - 1) + 1);
    const float az = __ldg(coords + 3 * (N_FIXED - 1) + 2);

    // p0=(c0.x,c0.y,c0.z) p1=(c0.w,c1.x,c1.y) p2=(c1.z,c1.w,c2.x) p3=(c2.y,c2.z,c2.w)
    float v;
    v  = pair_loss(ax, ay, az, al, c0.x, c0.y, c0.z, lab.x);
    v += pair_loss(ax, ay, az, al, c0.w, c1.x, c1.y, lab.y);
    v += pair_loss(ax, ay, az, al, c1.z, c1.w, c2.x, lab.z);
    v += pair_loss(ax, ay, az, al, c2.y, c2.z, c2.w, lab.w);

    #pragma unroll
    for (int o = 16; o > 0; o >>= 1)
        v += __shfl_down_sync(0xFFFFFFFFu, v, o);

    if ((threadIdx.x & 31) == 0)
        red_add_f32_relaxed(out, v);   // fire-and-forget; warp exits immediately
}

// ---- Generic fallback for any n (correctness safety net). ----
__global__ __launch_bounds__(TPB)
void loss_kernel_generic(const int* __restrict__ labels,
                         const float* __restrict__ coords,
                         float* __restrict__ out,
                         int n)
{
    const int base = (blockIdx.x * TPB + threadIdx.x) * PTS_PER_THREAD;

    const int   al = __ldg(labels + (n - 1));
    const float ax = __ldg(coords + 3 * (n - 1) + 0);
    const float ay = __ldg(coords + 3 * (n - 1) + 1);
    const float az = __ldg(coords + 3 * (n - 1) + 2);

    float v = 0.0f;
    for (int i = base; i < n && i < base + PTS_PER_THREAD; i++)
        v += pair_loss(ax, ay, az, al,
                       coords[3 * i + 0], coords[3 * i + 1], coords[3 * i + 2],
                       labels[i]);

    #pragma unroll
    for (int o = 16; o > 0; o >>= 1)
        v += __shfl_down_sync(0xFFFFFFFFu, v, o);

    if ((threadIdx.x & 31) == 0)
        red_add_f32_relaxed(out, v);
}

extern "C" void kernel_launch(void* const* d_in, const int* in_sizes, int n_in,
                              void* d_out, int out_size)
{
    const int*   labels = (const int*)d_in[0];
    const float* coords = (const float*)d_in[1];
    float*       out    = (float*)d_out;
    const int n = in_sizes[0];

    zero_out_kernel<<<1, 1>>>(out);

    if (n == N_FIXED) {
        loss_kernel_32768<<<BLOCKS_FIXED, TPB>>>(labels, coords, out);
    } else {
        const int pts_per_cta = TPB * PTS_PER_THREAD;
        const int blocks = (n + pts_per_cta - 1) / pts_per_cta;
        loss_kernel_generic<<<blocks, TPB>>>(labels, coords, out, n);
    }
}